// round 4
// baseline (speedup 1.0000x reference)
#include <cuda_runtime.h>
#include <cuda_bf16.h>
#include <math.h>
#include <stdint.h>

#define NB 16
#define NS 16384
#define NC 64
#define NM 16
#define NPSP 500
#define NPFR 200
#define NED 8
#define NCH 32          // DFT chunks over s (512 s each)

// -------- scratch (static device globals; no runtime allocation) -----------
__device__ float g_h[NB * NS * NC];                 // [b][s][c]  64 MB
__device__ float g_tw[NS * 32];                     // per s: cos[16], sin[16]
__device__ float g_sc[NB * NS];                     // channel sums
__device__ int   g_idx[NB * NS];                    // spatial engram idx
__device__ float g_xpart[NB * NCH * NC * 32];       // DFT partials (4 MB)
__device__ float g_epart[NB * 64 * NED];            // embedding partial sums
__device__ float g_cR[NB * NC * NM];                // combined mode coef (pre-scaled)
__device__ float g_cI[NB * NC * NM];
__device__ float g_w0[NB];                          // gate weight for sp branch

// ---------------------------------------------------------------------------
__global__ void k_twiddle() {
    int s = blockIdx.x * 256 + threadIdx.x;
    if (s >= NS) return;
#pragma unroll
    for (int k = 0; k < 16; k++) {
        int r = (k * s) & (NS - 1);
        double a = (double)r * (2.0 * 3.141592653589793238 / (double)NS);
        double sd, cd; sincos(a, &sd, &cd);
        g_tw[s * 32 + k]      = (float)cd;
        g_tw[s * 32 + 16 + k] = (float)sd;
    }
}

// lifting: h[b,s,c] = sum_ci x[b,ci,s] * W[ci,c] + bias[c]
__global__ void k_lift(const float* __restrict__ x,
                       const float* __restrict__ W,
                       const float* __restrict__ bias) {
    __shared__ float lw[3 * NC], lb[NC];
    int b = blockIdx.y, t = threadIdx.x;
    if (t < 192) lw[t] = W[t];
    if (t < NC)  lb[t] = bias[t];
    __syncthreads();
    int c = t & 63, sg = t >> 6;
    const float* xb = x + b * 3 * NS;
    for (int i = 0; i < 16; i++) {
        int s = blockIdx.x * 64 + i * 4 + sg;
        float x0 = xb[s], x1 = xb[NS + s], x2 = xb[2 * NS + s];
        g_h[(b * NS + s) * NC + c] = lb[c] + x0 * lw[c] + x1 * lw[64 + c] + x2 * lw[128 + c];
    }
}

// sC[b,s] = sequential sum over 64 channels
__global__ void k_sc() {
    int b = blockIdx.y;
    int s = blockIdx.x * 256 + threadIdx.x;
    const float4* hp = (const float4*)(g_h + (b * NS + s) * NC);
    float acc = 0.0f;
#pragma unroll
    for (int q = 0; q < 16; q++) {
        float4 v = hp[q];
        acc += v.x; acc += v.y; acc += v.z; acc += v.w;
    }
    g_sc[b * NS + s] = acc;
}

// spatial hash idx + block-partial embedding sums
__global__ void k_idx(const float* __restrict__ sp_emb, int layer) {
    __shared__ float red[256];
    int b = blockIdx.y, t = threadIdx.x;
    int s = blockIdx.x * 256 + t;
    const float* sc = g_sc + b * NS;
    int a0 = s - 2 < 0 ? 0 : s - 2;
    int a1 = s - 1 < 0 ? 0 : s - 1;
    int a3 = s + 1 > NS - 1 ? NS - 1 : s + 1;
    float w = ((sc[a0] + sc[a1]) + sc[s]) + sc[a3];
    int iv = (int)(w * 31.0f);
    iv = ((iv % NPSP) + NPSP) % NPSP;
    g_idx[b * NS + s] = iv;
    const float* em = sp_emb + (layer * NPSP + iv) * NED;
    float ev[NED];
#pragma unroll
    for (int e = 0; e < NED; e++) ev[e] = em[e];
#pragma unroll
    for (int e = 0; e < NED; e++) {
        red[t] = ev[e];
        __syncthreads();
        for (int off = 128; off > 0; off >>= 1) {
            if (t < off) red[t] += red[t + off];
            __syncthreads();
        }
        if (t == 0) g_epart[(b * 64 + blockIdx.x) * NED + e] = red[0];
        __syncthreads();
    }
}

// 16-mode DFT partials: per (b, chunk) block, 256 thr (c = t&63, group = t>>6)
__global__ void k_dft() {
    __shared__ float red[256 * 32];
    int b = blockIdx.y, chunk = blockIdx.x, t = threadIdx.x;
    int c = t & 63, g = t >> 6;
    float aC[16], aS[16];
#pragma unroll
    for (int k = 0; k < 16; k++) { aC[k] = 0.f; aS[k] = 0.f; }
    const float* hb = g_h + b * NS * NC + c;
    for (int i = 0; i < 128; i++) {
        int s = chunk * 512 + i * 4 + g;
        float xv = hb[s * NC];
        const float4* tw = (const float4*)(g_tw + s * 32);
#pragma unroll
        for (int q = 0; q < 4; q++) {
            float4 tc = tw[q];
            aC[4*q+0] += xv * tc.x; aC[4*q+1] += xv * tc.y;
            aC[4*q+2] += xv * tc.z; aC[4*q+3] += xv * tc.w;
        }
#pragma unroll
        for (int q = 0; q < 4; q++) {
            float4 ts = tw[4 + q];
            aS[4*q+0] += xv * ts.x; aS[4*q+1] += xv * ts.y;
            aS[4*q+2] += xv * ts.z; aS[4*q+3] += xv * ts.w;
        }
    }
#pragma unroll
    for (int k = 0; k < 16; k++) { red[t * 32 + k] = aC[k]; red[t * 32 + 16 + k] = aS[k]; }
    __syncthreads();
    if (g == 0) {
        float* dst = g_xpart + ((b * NCH + chunk) * NC + c) * 32;
#pragma unroll
        for (int k = 0; k < 32; k++)
            dst[k] = ((red[c*32+k] + red[(64+c)*32+k]) + red[(128+c)*32+k]) + red[(192+c)*32+k];
    }
}

// per-b small math: X reduce, mags+fr hash, mh einsum, fr proj, gate MLP, coef combine
__global__ void k_small(const float* __restrict__ sp_W, const float* __restrict__ sp_b,
                        const float* __restrict__ fr_emb, const float* __restrict__ fr_W,
                        const float* __restrict__ fr_b,
                        const float* __restrict__ gW1, const float* __restrict__ gb1,
                        const float* __restrict__ gW2, const float* __restrict__ gb2,
                        const float* __restrict__ Wr, const float* __restrict__ Wi,
                        int layer) {
    __shared__ float sXR[1024], sXI[1024], sOR[1024], sOI[1024], sPR[1024];
    __shared__ float sMag[16], sEmb[8], sEm[8], sG[192], sH1[64], sW[3];
    __shared__ int sFidx;
    int b = blockIdx.x, t = threadIdx.x;
    const float invS = 1.0f / (float)NS;

    // reduce DFT partials over chunks
    for (int it = 0; it < 4; it++) {
        int p = t + it * 256;            // p = c*16 + k
        int c = p >> 4, k = p & 15;
        float sc_ = 0.f, ss = 0.f;
        for (int ch = 0; ch < NCH; ch++) {
            const float* src = g_xpart + ((b * NCH + ch) * NC + c) * 32 + k;
            sc_ += src[0]; ss += src[16];
        }
        sXR[p] = sc_; sXI[p] = -ss;      // rfft: Im = -sum x*sin
    }
    __syncthreads();

    // spectral magnitudes (mean over channels, sequential) + fr hash
    if (t < 16) {
        float acc = 0.f;
        for (int c = 0; c < NC; c++) {
            float xr = sXR[c * 16 + t], xi = sXI[c * 16 + t];
            acc += sqrtf(xr * xr + xi * xi);
        }
        sMag[t] = acc * (1.0f / 64.0f);
    }
    __syncthreads();
    if (t == 0) {
        int s = 0;
        for (int m = 0; m < 16; m++) s += (int)(sMag[m] * 1000.0f);
        sFidx = ((s % NPFR) + NPFR) % NPFR;
    }
    __syncthreads();
    if (t < 8) sEmb[t] = fr_emb[(layer * NPFR + sFidx) * NED + t];

    // mh einsum: of[h,o,m] = sum_i X[h*16+i,m] * Wc[h,i,o,m]
    for (int it = 0; it < 4; it++) {
        int p = t + it * 256;
        int oc = p >> 4, m = p & 15;
        int hh = oc >> 4, o = oc & 15;
        float aR = 0.f, aI = 0.f;
        for (int i = 0; i < 16; i++) {
            float xr = sXR[(hh * 16 + i) * 16 + m];
            float xi = sXI[(hh * 16 + i) * 16 + m];
            int wi_ = (((layer * 4 + hh) * 16 + i) * 16 + o) * 16 + m;
            float wr = Wr[wi_], wim = Wi[wi_];
            aR += xr * wr - xi * wim;
            aI += xr * wim + xi * wr;
        }
        sOR[p] = aR; sOI[p] = aI;
    }
    __syncthreads();

    // fr projection coefficients (real)
    for (int it = 0; it < 4; it++) {
        int p = t + it * 256;
        int c = p >> 4, m = p & 15;
        float acc = fr_b[layer * 1024 + c * 16 + m];
        for (int e = 0; e < NED; e++)
            acc += sEmb[e] * fr_W[(layer * NED + e) * 1024 + c * 16 + m];
        sPR[p] = acc;
    }

    // embedding mean
    if (t < 8) {
        float acc = 0.f;
        for (int blk = 0; blk < 64; blk++) acc += g_epart[(b * 64 + blk) * NED + t];
        sEm[t] = acc * invS;
    }
    __syncthreads();

    // gate input vector [sp_mean | mh_mean | fr_mean]
    if (t < 64) {
        float sm = sp_b[layer * NC + t];
        for (int e = 0; e < NED; e++) sm += sEm[e] * sp_W[(layer * NED + e) * NC + t];
        sG[t]       = sm;
        sG[64 + t]  = sOR[t * 16] * invS;
        sG[128 + t] = sPR[t * 16] * invS;
    }
    __syncthreads();
    if (t < 64) {
        float acc = gb1[layer * 64 + t];
        for (int i = 0; i < 192; i++) acc += sG[i] * gW1[(layer * 192 + i) * 64 + t];
        sH1[t] = fmaxf(acc, 0.0f);
    }
    __syncthreads();
    if (t < 3) {
        float acc = gb2[layer * 3 + t];
        for (int i = 0; i < 64; i++) acc += sH1[i] * gW2[(layer * 64 + i) * 3 + t];
        sW[t] = acc;
    }
    __syncthreads();
    if (t == 0) {
        float mx = fmaxf(sW[0], fmaxf(sW[1], sW[2]));
        float e0 = expf(sW[0] - mx), e1 = expf(sW[1] - mx), e2 = expf(sW[2] - mx);
        float inv = 1.0f / (e0 + e1 + e2);
        sW[0] = e0 * inv; sW[1] = e1 * inv; sW[2] = e2 * inv;
        g_w0[b] = sW[0];
    }
    __syncthreads();

    // combined, pre-scaled mode coefficients
    float w1 = sW[1], w2 = sW[2];
    for (int it = 0; it < 4; it++) {
        int p = t + it * 256;
        int k = p & 15;
        float scale = (k == 0) ? invS : 2.0f * invS;
        g_cR[b * 1024 + p] = (w1 * sOR[p] + w2 * sPR[p]) * scale;
        g_cI[b * 1024 + p] = (w1 * sOI[p]) * scale;
    }
}

// fused synthesis: h = gelu( w0*sp + sum_k (cR cos - cI sin) ), in place
__global__ void k_synth(const float* __restrict__ sp_emb,
                        const float* __restrict__ sp_W,
                        const float* __restrict__ sp_b, int layer) {
    __shared__ float sw[NED * NC], sb[NC];
    int b = blockIdx.y, t = threadIdx.x;
    for (int p = t; p < NED * NC; p += 256) sw[p] = sp_W[layer * NED * NC + p];
    if (t < NC) sb[t] = sp_b[layer * NC + t];
    __syncthreads();
    int c = t & 63, sg = t >> 6;
    float cR[16], cI[16];
    const float* crp = g_cR + (b * NC + c) * NM;
    const float* cip = g_cI + (b * NC + c) * NM;
#pragma unroll
    for (int k = 0; k < 16; k++) { cR[k] = crp[k]; cI[k] = cip[k]; }
    float w0 = g_w0[b];
    for (int i = 0; i < 32; i++) {
        int s = blockIdx.x * 128 + i * 4 + sg;
        int iv = g_idx[b * NS + s];
        const float* em = sp_emb + (layer * NPSP + iv) * NED;
        float spv = sb[c];
#pragma unroll
        for (int e = 0; e < NED; e++) spv += em[e] * sw[e * NC + c];
        const float4* tw = (const float4*)(g_tw + s * 32);
        float spec = 0.f;
#pragma unroll
        for (int q = 0; q < 4; q++) {
            float4 tc = tw[q];
            spec += cR[4*q+0]*tc.x + cR[4*q+1]*tc.y + cR[4*q+2]*tc.z + cR[4*q+3]*tc.w;
        }
#pragma unroll
        for (int q = 0; q < 4; q++) {
            float4 ts = tw[4 + q];
            spec -= cI[4*q+0]*ts.x + cI[4*q+1]*ts.y + cI[4*q+2]*ts.z + cI[4*q+3]*ts.w;
        }
        float v = w0 * spv + spec;
        float gl = 0.5f * v * (1.0f + erff(v * 0.70710678118654752f));
        g_h[(b * NS + s) * NC + c] = gl;
    }
}

// projection: out[b,0,s] = sum_c h[b,s,c] * Wp[c] + bp
__global__ void k_proj(const float* __restrict__ Wp, const float* __restrict__ bp,
                       float* __restrict__ out) {
    __shared__ float pw[NC];
    int b = blockIdx.y, t = threadIdx.x;
    if (t < NC) pw[t] = Wp[t];
    __syncthreads();
    int s = blockIdx.x * 256 + t;
    const float* hp = g_h + (b * NS + s) * NC;
    float acc = 0.f;
    for (int c = 0; c < NC; c++) acc += hp[c] * pw[c];
    out[b * NS + s] = acc + bp[0];
}

extern "C" void kernel_launch(void* const* d_in, const int* in_sizes, int n_in,
                              void* d_out, int out_size) {
    const float* x      = (const float*)d_in[0];
    const float* lift_W = (const float*)d_in[1];
    const float* lift_b = (const float*)d_in[2];
    const float* proj_W = (const float*)d_in[3];
    const float* proj_b = (const float*)d_in[4];
    const float* sp_emb = (const float*)d_in[5];
    const float* sp_W   = (const float*)d_in[6];
    const float* sp_b   = (const float*)d_in[7];
    const float* fr_emb = (const float*)d_in[8];
    const float* fr_W   = (const float*)d_in[9];
    const float* fr_b   = (const float*)d_in[10];
    const float* g_W1   = (const float*)d_in[11];
    const float* g_b1   = (const float*)d_in[12];
    const float* g_W2   = (const float*)d_in[13];
    const float* g_b2   = (const float*)d_in[14];
    const float* mhf_Wr = (const float*)d_in[15];
    const float* mhf_Wi = (const float*)d_in[16];
    float* out = (float*)d_out;

    k_twiddle<<<NS / 256, 256>>>();
    k_lift<<<dim3(NS / 64, NB), 256>>>(x, lift_W, lift_b);
    for (int l = 0; l < 4; l++) {
        k_sc<<<dim3(NS / 256, NB), 256>>>();
        k_idx<<<dim3(NS / 256, NB), 256>>>(sp_emb, l);
        k_dft<<<dim3(NCH, NB), 256>>>();
        k_small<<<NB, 256>>>(sp_W, sp_b, fr_emb, fr_W, fr_b,
                             g_W1, g_b1, g_W2, g_b2, mhf_Wr, mhf_Wi, l);
        k_synth<<<dim3(NS / 128, NB), 256>>>(sp_emb, sp_W, sp_b, l);
    }
    k_proj<<<dim3(NS / 256, NB), 256>>>(proj_W, proj_b, out);
}